// round 16
// baseline (speedup 1.0000x reference)
#include <cuda_runtime.h>
#include <cuda_fp16.h>
#include <math.h>

// ---- problem dims (compile-time capacity; runtime values read from in_sizes) ----
#define NMAX 100000
#define EMAX 1000000
#define HF   64          // hidden features
#define GMAX 256
#define NB_SCAN 128      // >= ceil(NMAX/1024)

// ---- device scratch (allocation-free rule: __device__ globals) ----
// INVARIANT: g_deg and g_cursor are all-zero at kernel_launch entry.
// (Zero-initialized at module load; k_scan_final re-zeroes g_deg after
//  consuming it and zeroes g_cursor before k_scatter increments it.)
__device__ float   g_h0[NMAX * HF];       // h0 = xW+b (fp32 anchor, final hop)
__device__ __half2 g_h0h[NMAX * HF / 2];  // fp16 h0 (non-final hops)
__device__ __half2 g_uA[NMAX * HF / 2];   // u = dinv*h, fp16 (gathered state)
__device__ __half2 g_uB[NMAX * HF / 2];   // double buffer; final hop: h (fp16)
__device__ float   g_dinv[NMAX];
__device__ int     g_deg[NMAX];
__device__ int     g_roff[NMAX + 1];
__device__ int     g_cursor[NMAX];
__device__ int     g_ccol[EMAX];          // col-only CSR (weights factored out)
__device__ float   g_v[NMAX];
__device__ float   g_z[GMAX * 2 * HF];
__device__ int     g_bsum[NB_SCAN];

// ---------------------------------------------------------------------------
// 1) degree histogram over edge rows; relies on g_deg == 0 on entry
__global__ void k_hist(const int* __restrict__ row, int e) {
    int i = blockIdx.x * blockDim.x + threadIdx.x;
    if (i < e) atomicAdd(&g_deg[row[i]], 1);
}

// 2) per-1024-block sums of deg (int4) + fused dinv computation
__global__ void k_scan_bsum(int n) {
    int t = threadIdx.x;                  // 256
    int i4 = blockIdx.x * 256 + t;
    int base = i4 * 4;
    int s = 0;
    if (base + 3 < n) {
        int4 d = ((const int4*)g_deg)[i4];
        s = d.x + d.y + d.z + d.w;
        float4 di;
        di.x = rsqrtf((float)(d.x + 1));
        di.y = rsqrtf((float)(d.y + 1));
        di.z = rsqrtf((float)(d.z + 1));
        di.w = rsqrtf((float)(d.w + 1));
        ((float4*)g_dinv)[i4] = di;
    } else {
        for (int j = base; j < n; j++) {
            int d = g_deg[j];
            s += d;
            g_dinv[j] = rsqrtf((float)(d + 1));
        }
    }
    #pragma unroll
    for (int o = 16; o > 0; o >>= 1) s += __shfl_xor_sync(0xFFFFFFFFu, s, o);
    __shared__ int r[8];
    if ((t & 31) == 0) r[t >> 5] = s;
    __syncthreads();
    if (t == 0) {
        int acc = 0;
        #pragma unroll
        for (int i = 0; i < 8; i++) acc += r[i];
        g_bsum[blockIdx.x] = acc;
    }
}

// 3) final exclusive scan -> row offsets; zero cursor; RE-ZERO deg (invariant)
__global__ void k_scan_final(int nb, int e, int n) {
    int t = threadIdx.x;                 // 256
    __shared__ int sboff;
    {
        int v = 0;
        if (t < NB_SCAN && t < blockIdx.x && t < nb) v = g_bsum[t];
        #pragma unroll
        for (int o = 16; o > 0; o >>= 1) v += __shfl_xor_sync(0xFFFFFFFFu, v, o);
        __shared__ int wr[8];
        if ((t & 31) == 0) wr[t >> 5] = v;
        __syncthreads();
        if (t == 0) {
            int acc = 0;
            #pragma unroll
            for (int i = 0; i < 8; i++) acc += wr[i];
            sboff = acc;
        }
        __syncthreads();
    }
    int base = blockIdx.x * 1024 + t * 4;
    int d0 = (base + 0 < n) ? g_deg[base + 0] : 0;
    int d1 = (base + 1 < n) ? g_deg[base + 1] : 0;
    int d2 = (base + 2 < n) ? g_deg[base + 2] : 0;
    int d3 = (base + 3 < n) ? g_deg[base + 3] : 0;
    int p1 = d0, p2 = d0 + d1, p3 = d0 + d1 + d2;
    int ts = p3 + d3;
    int lane = t & 31, w = t >> 5;
    int v = ts;
    #pragma unroll
    for (int o = 1; o < 32; o <<= 1) {
        int u = __shfl_up_sync(0xFFFFFFFFu, v, o);
        if (lane >= o) v += u;
    }
    __shared__ int wsum[8], woff[8];
    if (lane == 31) wsum[w] = v;
    __syncthreads();
    if (t == 0) {
        int acc = 0;
        for (int i = 0; i < 8; i++) { woff[i] = acc; acc += wsum[i]; }
    }
    __syncthreads();
    int excl = v - ts + woff[w] + sboff;
    if (base + 0 < n) { g_roff[base + 0] = excl;      g_cursor[base + 0] = 0; g_deg[base + 0] = 0; }
    if (base + 1 < n) { g_roff[base + 1] = excl + p1; g_cursor[base + 1] = 0; g_deg[base + 1] = 0; }
    if (base + 2 < n) { g_roff[base + 2] = excl + p2; g_cursor[base + 2] = 0; g_deg[base + 2] = 0; }
    if (base + 3 < n) { g_roff[base + 3] = excl + p3; g_cursor[base + 3] = 0; g_deg[base + 3] = 0; }
    if (blockIdx.x == 0 && t == 0) g_roff[n] = e;
}

// 4) scatter edge cols into CSR — 1 edge/thread (R12 measured-best shape:
//    occupancy, not per-thread ILP, supplies the MLP here)
__global__ void k_scatter(const int* __restrict__ ei, int e) {
    int i = blockIdx.x * blockDim.x + threadIdx.x;
    if (i < e) {
        int r = ei[i];
        int c = ei[e + i];
        int pos = g_roff[r] + atomicAdd(&g_cursor[r], 1);
        g_ccol[pos] = c;
    }
}

// 5) h0 = x @ W_sgc + b_sgc (fp32 + fp16 copy); also u0 = fp16(dinv * h0)
__global__ void __launch_bounds__(128) k_gemm(
        const float* __restrict__ x, const float* __restrict__ W,
        const float* __restrict__ b, int n) {
    __shared__ float sxT[64][132];     // x transposed: [k][node], padded
    __shared__ float sW[64 * 64];      // W row-major [k][f]
    int t = threadIdx.x;               // 128 threads
    int base = blockIdx.x * 128;

    for (int i = t * 4; i < 4096; i += 512)
        *(float4*)&sW[i] = *(const float4*)&W[i];

    int gn = base + t;
    if (gn < n) {
        #pragma unroll
        for (int k = 0; k < 64; k += 4) {
            float4 v = *(const float4*)&x[gn * 64 + k];
            sxT[k + 0][t] = v.x;
            sxT[k + 1][t] = v.y;
            sxT[k + 2][t] = v.z;
            sxT[k + 3][t] = v.w;
        }
    } else {
        #pragma unroll
        for (int k = 0; k < 64; k++) sxT[k][t] = 0.f;
    }
    __syncthreads();

    int tx = t & 7, ty = t >> 3;       // 8 feature-groups x 16 node-groups
    int f0 = tx * 8, n0 = ty * 8;
    float acc[8][8];
    #pragma unroll
    for (int j = 0; j < 8; j++) {
        float bj = b[f0 + j];
        #pragma unroll
        for (int i = 0; i < 8; i++) acc[i][j] = bj;
    }
    #pragma unroll 4
    for (int k = 0; k < 64; k++) {
        float a[8], bb[8];
        *(float4*)&a[0]  = *(float4*)&sxT[k][n0];
        *(float4*)&a[4]  = *(float4*)&sxT[k][n0 + 4];
        *(float4*)&bb[0] = *(float4*)&sW[k * 64 + f0];
        *(float4*)&bb[4] = *(float4*)&sW[k * 64 + f0 + 4];
        #pragma unroll
        for (int i = 0; i < 8; i++)
            #pragma unroll
            for (int j = 0; j < 8; j++)
                acc[i][j] = fmaf(a[i], bb[j], acc[i][j]);
    }
    #pragma unroll
    for (int i = 0; i < 8; i++) {
        int gnode = base + n0 + i;
        if (gnode < n) {
            float d = g_dinv[gnode];
            float4* oh = (float4*)&g_h0[gnode * 64 + f0];
            oh[0] = make_float4(acc[i][0], acc[i][1], acc[i][2], acc[i][3]);
            oh[1] = make_float4(acc[i][4], acc[i][5], acc[i][6], acc[i][7]);
            // fp16 h0 copy
            __half2 h01 = __floats2half2_rn(acc[i][0], acc[i][1]);
            __half2 h23 = __floats2half2_rn(acc[i][2], acc[i][3]);
            __half2 h45 = __floats2half2_rn(acc[i][4], acc[i][5]);
            __half2 h67 = __floats2half2_rn(acc[i][6], acc[i][7]);
            uint4 hp;
            hp.x = *(unsigned int*)&h01;
            hp.y = *(unsigned int*)&h23;
            hp.z = *(unsigned int*)&h45;
            hp.w = *(unsigned int*)&h67;
            *(uint4*)&g_h0h[gnode * 32 + f0 / 2] = hp;
            // fp16 u0 = d * h0
            __half2 u01 = __floats2half2_rn(d * acc[i][0], d * acc[i][1]);
            __half2 u23 = __floats2half2_rn(d * acc[i][2], d * acc[i][3]);
            __half2 u45 = __floats2half2_rn(d * acc[i][4], d * acc[i][5]);
            __half2 u67 = __floats2half2_rn(d * acc[i][6], d * acc[i][7]);
            uint4 up;
            up.x = *(unsigned int*)&u01;
            up.y = *(unsigned int*)&u23;
            up.z = *(unsigned int*)&u45;
            up.w = *(unsigned int*)&u67;
            *(uint4*)&g_uA[gnode * 32 + f0 / 2] = up;
        }
    }
}

// accumulate 8 fp16 features (one uint4 = 128 bits) into 8 fp32 accumulators
__device__ __forceinline__ void acc8(float* S, uint4 a) {
    float2 f;
    f = __half22float2(*(__half2*)&a.x); S[0] += f.x; S[1] += f.y;
    f = __half22float2(*(__half2*)&a.y); S[2] += f.x; S[3] += f.y;
    f = __half22float2(*(__half2*)&a.z); S[4] += f.x; S[5] += f.y;
    f = __half22float2(*(__half2*)&a.w); S[6] += f.x; S[7] += f.y;
}

// 6) one propagation hop on fp16 u = dinv*h:  S = sum_c u[c]
//    QUARTER-warp per edge: 8 lanes x uint4(16B) = 128B row, so one row
//    LDG.128 covers FOUR edges per instruction (halves issue count/edge vs
//    the LDG.64 layout; LTS bytes unchanged). Cross-quarter combine = 2
//    shfl rounds. h' = 0.5*d*(S+u_i) + 0.5*h0 ; u' = fp16(d*h').
//    Non-final hops read fp16 h0; FINAL reads fp32 h0, writes fp16 h -> uB.
template<int SRC, bool FINAL>
__global__ void __launch_bounds__(256) k_hop(const float* __restrict__ w_att,
                                             const float* __restrict__ b_att,
                                             int n) {
    int wid = (blockIdx.x * blockDim.x + threadIdx.x) >> 5;
    if (wid >= n) return;
    int lane = threadIdx.x & 31;
    int qw = lane >> 3, ql = lane & 7;      // quarter id, lane-in-quarter

    const uint4* uin = (const uint4*)(SRC == 1 ? g_uB : g_uA);

    float d = g_dinv[wid];
    uint4 usr = uin[wid * 8 + ql];          // u self: 8 features per lane

    float S[8] = {0.f, 0.f, 0.f, 0.f, 0.f, 0.f, 0.f, 0.f};
    int s = g_roff[wid], e = g_roff[wid + 1];
    int p = s;
    for (; p + 4 <= e; p += 4) {            // 4 edges per iteration (1/quarter)
        int c = g_ccol[p + qw];
        uint4 a = uin[c * 8 + ql];
        acc8(S, a);
    }
    if (p < e) {                            // tail: up to 3 edges, guarded
        int idx = p + qw;
        if (idx < e) {
            int c = g_ccol[idx];
            uint4 a = uin[c * 8 + ql];
            acc8(S, a);
        }
    }
    // combine the four quarters (same feature slice ql across quarters)
    #pragma unroll
    for (int j = 0; j < 8; j++) {
        S[j] += __shfl_xor_sync(0xFFFFFFFFu, S[j], 8);
        S[j] += __shfl_xor_sync(0xFFFFFFFFu, S[j], 16);
    }

    float us[8];
    {
        float2 f;
        f = __half22float2(*(__half2*)&usr.x); us[0] = f.x; us[1] = f.y;
        f = __half22float2(*(__half2*)&usr.y); us[2] = f.x; us[3] = f.y;
        f = __half22float2(*(__half2*)&usr.z); us[4] = f.x; us[5] = f.y;
        f = __half22float2(*(__half2*)&usr.w); us[6] = f.x; us[7] = f.y;
    }

    float h0[8];
    if (FINAL) {
        float4 a = ((const float4*)g_h0)[wid * 16 + ql * 2];
        float4 bq = ((const float4*)g_h0)[wid * 16 + ql * 2 + 1];
        h0[0] = a.x;  h0[1] = a.y;  h0[2] = a.z;  h0[3] = a.w;
        h0[4] = bq.x; h0[5] = bq.y; h0[6] = bq.z; h0[7] = bq.w;
    } else {
        uint4 hr = ((const uint4*)g_h0h)[wid * 8 + ql];
        float2 f;
        f = __half22float2(*(__half2*)&hr.x); h0[0] = f.x; h0[1] = f.y;
        f = __half22float2(*(__half2*)&hr.y); h0[2] = f.x; h0[3] = f.y;
        f = __half22float2(*(__half2*)&hr.z); h0[4] = f.x; h0[5] = f.y;
        f = __half22float2(*(__half2*)&hr.w); h0[6] = f.x; h0[7] = f.y;
    }

    float o[8];
    #pragma unroll
    for (int j = 0; j < 8; j++)
        o[j] = 0.5f * d * (S[j] + us[j]) + 0.5f * h0[j];

    if (FINAL) {
        #pragma unroll
        for (int j = 0; j < 8; j++) o[j] = fmaxf(o[j], 0.f);
        float4 wa0 = ((const float4*)w_att)[ql * 2];
        float4 wa1 = ((const float4*)w_att)[ql * 2 + 1];
        float dp = o[0] * wa0.x + o[1] * wa0.y + o[2] * wa0.z + o[3] * wa0.w
                 + o[4] * wa1.x + o[5] * wa1.y + o[6] * wa1.z + o[7] * wa1.w;
        #pragma unroll
        for (int off = 4; off > 0; off >>= 1)
            dp += __shfl_xor_sync(0xFFFFFFFFu, dp, off);   // reduce over ql
        if (lane == 0) g_v[wid] = 1.f / (1.f + expf(-(dp + b_att[0])));
        if (qw == 0) {                                     // fp16 h -> uB
            __half2 p0 = __floats2half2_rn(o[0], o[1]);
            __half2 p1 = __floats2half2_rn(o[2], o[3]);
            __half2 p2 = __floats2half2_rn(o[4], o[5]);
            __half2 p3 = __floats2half2_rn(o[6], o[7]);
            uint4 raw;
            raw.x = *(unsigned int*)&p0;
            raw.y = *(unsigned int*)&p1;
            raw.z = *(unsigned int*)&p2;
            raw.w = *(unsigned int*)&p3;
            ((uint4*)g_uB)[wid * 8 + ql] = raw;
        }
    } else {
        if (qw == 0) {
            uint4* uout = (uint4*)(SRC == 0 ? g_uB : g_uA);
            __half2 p0 = __floats2half2_rn(d * o[0], d * o[1]);
            __half2 p1 = __floats2half2_rn(d * o[2], d * o[3]);
            __half2 p2 = __floats2half2_rn(d * o[4], d * o[5]);
            __half2 p3 = __floats2half2_rn(d * o[6], d * o[7]);
            uint4 raw;
            raw.x = *(unsigned int*)&p0;
            raw.y = *(unsigned int*)&p1;
            raw.z = *(unsigned int*)&p2;
            raw.w = *(unsigned int*)&p3;
            uout[wid * 8 + ql] = raw;                      // fp16 u'
        }
    }
}

__device__ __forceinline__ int lower_bound_i(const int* a, int n, int key) {
    int lo = 0, hi = n;
    while (lo < hi) {
        int mid = (lo + hi) >> 1;
        if (a[mid] < key) lo = mid + 1; else hi = mid;
    }
    return lo;
}

// 7) per-graph readout (fp16 h from g_uB): segments of sorted `batch`.
__global__ void __launch_bounds__(128) k_readout(const int* __restrict__ batch, int n) {
    int g = blockIdx.x;
    int t = threadIdx.x;              // 128 threads
    __shared__ int sse[2];
    if (t == 0) sse[0] = lower_bound_i(batch, n, g);
    if (t == 1) sse[1] = lower_bound_i(batch, n, g + 1);
    __syncthreads();
    int s = sse[0], e = sse[1];

    __shared__ float red[128];
    float lm = -INFINITY;
    for (int i = s + t; i < e; i += 128) lm = fmaxf(lm, g_v[i]);
    red[t] = lm; __syncthreads();
    for (int o = 64; o > 0; o >>= 1) { if (t < o) red[t] = fmaxf(red[t], red[t + o]); __syncthreads(); }
    float vmax = red[0];
    __syncthreads();
    float ls = 0.f;
    for (int i = s + t; i < e; i += 128) ls += expf(g_v[i] - vmax);
    red[t] = ls; __syncthreads();
    for (int o = 64; o > 0; o >>= 1) { if (t < o) red[t] += red[t + o]; __syncthreads(); }
    float inv = 1.f / (red[0] + 1e-16f);
    __syncthreads();

    int hl = t & 15, r8 = t >> 4;
    const uint2* h2 = (const uint2*)g_uB;
    float4 gmax = make_float4(-INFINITY, -INFINITY, -INFINITY, -INFINITY);
    float4 gsum = make_float4(0.f, 0.f, 0.f, 0.f);
    for (int i = s + r8; i < e; i += 8) {
        float ev = expf(g_v[i] - vmax);
        uint2 hr = h2[i * 16 + hl];
        float2 f01 = __half22float2(*(__half2*)&hr.x);
        float2 f23 = __half22float2(*(__half2*)&hr.y);
        gmax.x = fmaxf(gmax.x, f01.x); gmax.y = fmaxf(gmax.y, f01.y);
        gmax.z = fmaxf(gmax.z, f23.x); gmax.w = fmaxf(gmax.w, f23.y);
        gsum.x = fmaf(ev, f01.x, gsum.x); gsum.y = fmaf(ev, f01.y, gsum.y);
        gsum.z = fmaf(ev, f23.x, gsum.z); gsum.w = fmaf(ev, f23.y, gsum.w);
    }
    __shared__ float4 smax[128], ssum[128];
    smax[t] = gmax; ssum[t] = gsum;
    __syncthreads();
    if (r8 == 0) {
        #pragma unroll
        for (int j = 1; j < 8; j++) {
            float4 m = smax[hl + 16 * j], sv = ssum[hl + 16 * j];
            gmax.x = fmaxf(gmax.x, m.x); gmax.y = fmaxf(gmax.y, m.y);
            gmax.z = fmaxf(gmax.z, m.z); gmax.w = fmaxf(gmax.w, m.w);
            gsum.x += sv.x; gsum.y += sv.y; gsum.z += sv.z; gsum.w += sv.w;
        }
        ((float4*)&g_z[g * 128])[hl] = gmax;
        gsum.x *= inv; gsum.y *= inv; gsum.z *= inv; gsum.w *= inv;
        ((float4*)&g_z[g * 128 + 64])[hl] = gsum;
    }
}

// 8) MLP head + log_softmax (one block of 64 threads per graph)
__global__ void k_mlp(const float* __restrict__ W1, const float* __restrict__ b1,
                      const float* __restrict__ W2, const float* __restrict__ b2,
                      const float* __restrict__ W3, const float* __restrict__ b3,
                      float* __restrict__ out) {
    int g = blockIdx.x, t = threadIdx.x;   // 64 threads
    __shared__ float sz[128], s1[64], s2[32], s3[8], lse;
    sz[t] = g_z[g * 128 + t];
    sz[t + 64] = g_z[g * 128 + 64 + t];
    __syncthreads();
    float a = b1[t];
    #pragma unroll 8
    for (int k = 0; k < 128; k++) a = fmaf(sz[k], W1[k * 64 + t], a);
    s1[t] = fmaxf(a, 0.f);
    __syncthreads();
    if (t < 32) {
        float a2 = b2[t];
        #pragma unroll 8
        for (int k = 0; k < 64; k++) a2 = fmaf(s1[k], W2[k * 32 + t], a2);
        s2[t] = fmaxf(a2, 0.f);
    }
    __syncthreads();
    if (t < 8) {
        float a3 = b3[t];
        #pragma unroll
        for (int k = 0; k < 32; k++) a3 = fmaf(s2[k], W3[k * 8 + t], a3);
        s3[t] = a3;
    }
    __syncthreads();
    if (t == 0) {
        float m = s3[0];
        for (int c = 1; c < 8; c++) m = fmaxf(m, s3[c]);
        float ss = 0.f;
        for (int c = 0; c < 8; c++) ss += expf(s3[c] - m);
        lse = m + logf(ss);
    }
    __syncthreads();
    if (t < 8) out[g * 8 + t] = s3[t] - lse;
}

extern "C" void kernel_launch(void* const* d_in, const int* in_sizes, int n_in,
                              void* d_out, int out_size) {
    const float* x     = (const float*)d_in[0];
    const int*   ei    = (const int*)  d_in[1];   // [2, E] flattened
    const int*   batch = (const int*)  d_in[2];
    const float* W_sgc = (const float*)d_in[3];
    const float* b_sgc = (const float*)d_in[4];
    const float* w_att = (const float*)d_in[5];
    const float* b_att = (const float*)d_in[6];
    const float* W1    = (const float*)d_in[7];
    const float* b1    = (const float*)d_in[8];
    const float* W2    = (const float*)d_in[9];
    const float* b2    = (const float*)d_in[10];
    const float* W3    = (const float*)d_in[11];
    const float* b3    = (const float*)d_in[12];
    float* out = (float*)d_out;

    int n = in_sizes[0] / HF;        // nodes
    int e = in_sizes[1] / 2;         // edges
    int g = out_size / 8;            // graphs

    int nb = (n + 1023) / 1024;      // 1024-element scan blocks

    k_hist<<<(e + 255) / 256, 256>>>(ei, e);                  // 1
    k_scan_bsum<<<nb, 256>>>(n);                              // 2
    k_scan_final<<<nb, 256>>>(nb, e, n);                      // 3
    k_scatter<<<(e + 255) / 256, 256>>>(ei, e);               // 4
    k_gemm<<<(n + 127) / 128, 128>>>(x, W_sgc, b_sgc, n);     // 5

    int hop_blocks = (n * 32 + 255) / 256;
    k_hop<0, false><<<hop_blocks, 256>>>(w_att, b_att, n);    // 6: uA -> uB
    k_hop<1, false><<<hop_blocks, 256>>>(w_att, b_att, n);    // 7: uB -> uA
    k_hop<2, true ><<<hop_blocks, 256>>>(w_att, b_att, n);    // 8: uA -> uB(h)

    k_readout<<<g, 128>>>(batch, n);                          // 9
    k_mlp<<<g, 64>>>(W1, b1, W2, b2, W3, b3, out);            // 10
}

// round 17
// speedup vs baseline: 1.1351x; 1.1351x over previous
#include <cuda_runtime.h>
#include <cuda_fp16.h>
#include <math.h>

// ---- problem dims (compile-time capacity; runtime values read from in_sizes) ----
#define NMAX 100000
#define EMAX 1000000
#define HF   64          // hidden features
#define GMAX 256
#define NB_SCAN 128      // >= ceil(NMAX/1024)

// ---- device scratch (allocation-free rule: __device__ globals) ----
// INVARIANT: g_deg and g_cursor are all-zero at kernel_launch entry.
// (Zero-initialized at module load; k_scan_final re-zeroes g_deg after
//  consuming it and zeroes g_cursor before k_scatter increments it.)
__device__ float   g_h0[NMAX * HF];      // h0 = xW+b (fp32 anchor)
__device__ float   g_hA[NMAX * HF];      // final h (readout input, fp32)
__device__ __half2 g_uA[NMAX * HF / 2];  // u = dinv*h, fp16 (gathered state)
__device__ __half2 g_uB[NMAX * HF / 2];
__device__ float   g_dinv[NMAX];
__device__ int     g_deg[NMAX];
__device__ int     g_roff[NMAX + 1];
__device__ int     g_cursor[NMAX];
__device__ int     g_ccol[EMAX];         // col-only CSR (weights factored out)
__device__ float   g_v[NMAX];
__device__ int     g_bsum[NB_SCAN];

// ---------------------------------------------------------------------------
// 1) degree histogram over edge rows; relies on g_deg == 0 on entry
__global__ void k_hist(const int* __restrict__ row, int e) {
    int i = blockIdx.x * blockDim.x + threadIdx.x;
    if (i < e) atomicAdd(&g_deg[row[i]], 1);
}

// 2) per-1024-block sums of deg (int4) + fused dinv computation
__global__ void k_scan_bsum(int n) {
    int t = threadIdx.x;                  // 256
    int i4 = blockIdx.x * 256 + t;
    int base = i4 * 4;
    int s = 0;
    if (base + 3 < n) {
        int4 d = ((const int4*)g_deg)[i4];
        s = d.x + d.y + d.z + d.w;
        float4 di;
        di.x = rsqrtf((float)(d.x + 1));
        di.y = rsqrtf((float)(d.y + 1));
        di.z = rsqrtf((float)(d.z + 1));
        di.w = rsqrtf((float)(d.w + 1));
        ((float4*)g_dinv)[i4] = di;
    } else {
        for (int j = base; j < n; j++) {
            int d = g_deg[j];
            s += d;
            g_dinv[j] = rsqrtf((float)(d + 1));
        }
    }
    #pragma unroll
    for (int o = 16; o > 0; o >>= 1) s += __shfl_xor_sync(0xFFFFFFFFu, s, o);
    __shared__ int r[8];
    if ((t & 31) == 0) r[t >> 5] = s;
    __syncthreads();
    if (t == 0) {
        int acc = 0;
        #pragma unroll
        for (int i = 0; i < 8; i++) acc += r[i];
        g_bsum[blockIdx.x] = acc;
    }
}

// 3) final exclusive scan -> row offsets; zero cursor; RE-ZERO deg (invariant)
__global__ void k_scan_final(int nb, int e, int n) {
    int t = threadIdx.x;                 // 256
    __shared__ int sboff;
    {
        int v = 0;
        if (t < NB_SCAN && t < blockIdx.x && t < nb) v = g_bsum[t];
        #pragma unroll
        for (int o = 16; o > 0; o >>= 1) v += __shfl_xor_sync(0xFFFFFFFFu, v, o);
        __shared__ int wr[8];
        if ((t & 31) == 0) wr[t >> 5] = v;
        __syncthreads();
        if (t == 0) {
            int acc = 0;
            #pragma unroll
            for (int i = 0; i < 8; i++) acc += wr[i];
            sboff = acc;
        }
        __syncthreads();
    }
    int base = blockIdx.x * 1024 + t * 4;
    int d0 = (base + 0 < n) ? g_deg[base + 0] : 0;
    int d1 = (base + 1 < n) ? g_deg[base + 1] : 0;
    int d2 = (base + 2 < n) ? g_deg[base + 2] : 0;
    int d3 = (base + 3 < n) ? g_deg[base + 3] : 0;
    int p1 = d0, p2 = d0 + d1, p3 = d0 + d1 + d2;
    int ts = p3 + d3;
    int lane = t & 31, w = t >> 5;
    int v = ts;
    #pragma unroll
    for (int o = 1; o < 32; o <<= 1) {
        int u = __shfl_up_sync(0xFFFFFFFFu, v, o);
        if (lane >= o) v += u;
    }
    __shared__ int wsum[8], woff[8];
    if (lane == 31) wsum[w] = v;
    __syncthreads();
    if (t == 0) {
        int acc = 0;
        for (int i = 0; i < 8; i++) { woff[i] = acc; acc += wsum[i]; }
    }
    __syncthreads();
    int excl = v - ts + woff[w] + sboff;
    if (base + 0 < n) { g_roff[base + 0] = excl;      g_cursor[base + 0] = 0; g_deg[base + 0] = 0; }
    if (base + 1 < n) { g_roff[base + 1] = excl + p1; g_cursor[base + 1] = 0; g_deg[base + 1] = 0; }
    if (base + 2 < n) { g_roff[base + 2] = excl + p2; g_cursor[base + 2] = 0; g_deg[base + 2] = 0; }
    if (base + 3 < n) { g_roff[base + 3] = excl + p3; g_cursor[base + 3] = 0; g_deg[base + 3] = 0; }
    if (blockIdx.x == 0 && t == 0) g_roff[n] = e;
}

// 4) scatter edge cols into CSR — 1 edge/thread (measured-best shape)
__global__ void k_scatter(const int* __restrict__ ei, int e) {
    int i = blockIdx.x * blockDim.x + threadIdx.x;
    if (i < e) {
        int r = ei[i];
        int c = ei[e + i];
        int pos = g_roff[r] + atomicAdd(&g_cursor[r], 1);
        g_ccol[pos] = c;
    }
}

// 5) h0 = x @ W_sgc + b_sgc (fp32); also u0 = fp16(dinv * h0)
__global__ void __launch_bounds__(128) k_gemm(
        const float* __restrict__ x, const float* __restrict__ W,
        const float* __restrict__ b, int n) {
    __shared__ float sxT[64][132];     // x transposed: [k][node], padded
    __shared__ float sW[64 * 64];      // W row-major [k][f]
    int t = threadIdx.x;               // 128 threads
    int base = blockIdx.x * 128;

    for (int i = t * 4; i < 4096; i += 512)
        *(float4*)&sW[i] = *(const float4*)&W[i];

    int gn = base + t;
    if (gn < n) {
        #pragma unroll
        for (int k = 0; k < 64; k += 4) {
            float4 v = *(const float4*)&x[gn * 64 + k];
            sxT[k + 0][t] = v.x;
            sxT[k + 1][t] = v.y;
            sxT[k + 2][t] = v.z;
            sxT[k + 3][t] = v.w;
        }
    } else {
        #pragma unroll
        for (int k = 0; k < 64; k++) sxT[k][t] = 0.f;
    }
    __syncthreads();

    int tx = t & 7, ty = t >> 3;       // 8 feature-groups x 16 node-groups
    int f0 = tx * 8, n0 = ty * 8;
    float acc[8][8];
    #pragma unroll
    for (int j = 0; j < 8; j++) {
        float bj = b[f0 + j];
        #pragma unroll
        for (int i = 0; i < 8; i++) acc[i][j] = bj;
    }
    #pragma unroll 4
    for (int k = 0; k < 64; k++) {
        float a[8], bb[8];
        *(float4*)&a[0]  = *(float4*)&sxT[k][n0];
        *(float4*)&a[4]  = *(float4*)&sxT[k][n0 + 4];
        *(float4*)&bb[0] = *(float4*)&sW[k * 64 + f0];
        *(float4*)&bb[4] = *(float4*)&sW[k * 64 + f0 + 4];
        #pragma unroll
        for (int i = 0; i < 8; i++)
            #pragma unroll
            for (int j = 0; j < 8; j++)
                acc[i][j] = fmaf(a[i], bb[j], acc[i][j]);
    }
    #pragma unroll
    for (int i = 0; i < 8; i++) {
        int gnode = base + n0 + i;
        if (gnode < n) {
            float d = g_dinv[gnode];
            float4* oh = (float4*)&g_h0[gnode * 64 + f0];
            oh[0] = make_float4(acc[i][0], acc[i][1], acc[i][2], acc[i][3]);
            oh[1] = make_float4(acc[i][4], acc[i][5], acc[i][6], acc[i][7]);
            __half2 u01 = __floats2half2_rn(d * acc[i][0], d * acc[i][1]);
            __half2 u23 = __floats2half2_rn(d * acc[i][2], d * acc[i][3]);
            __half2 u45 = __floats2half2_rn(d * acc[i][4], d * acc[i][5]);
            __half2 u67 = __floats2half2_rn(d * acc[i][6], d * acc[i][7]);
            uint4 up;
            up.x = *(unsigned int*)&u01;
            up.y = *(unsigned int*)&u23;
            up.z = *(unsigned int*)&u45;
            up.w = *(unsigned int*)&u67;
            *(uint4*)&g_uA[gnode * 32 + f0 / 2] = up;
        }
    }
}

__device__ __forceinline__ void acc_u(float4& S, uint2 raw) {
    float2 f01 = __half22float2(*(__half2*)&raw.x);
    float2 f23 = __half22float2(*(__half2*)&raw.y);
    S.x += f01.x; S.y += f01.y; S.z += f23.x; S.w += f23.y;
}

// 6) one propagation hop on fp16 u = dinv*h:  S = sum_c u[c]
//    h' = 0.5*d*(S + u_i) + 0.5*h0 (fp32);  u' = fp16(d*h')
//    warp per node, half-warp per edge (16 lanes x uint2 = 128B row),
//    2 edges in flight per half-warp — the R13-measured best loop shape.
//    FINAL: relu + v = sigmoid(h'.w_att+b_att), write fp32 h -> g_hA.
template<int SRC, bool FINAL>
__global__ void __launch_bounds__(256) k_hop(const float* __restrict__ w_att,
                                             const float* __restrict__ b_att,
                                             int n) {
    int wid = (blockIdx.x * blockDim.x + threadIdx.x) >> 5;
    if (wid >= n) return;
    int lane = threadIdx.x & 31;
    int half = lane >> 4, hl = lane & 15;

    const uint2* uin = (const uint2*)(SRC == 1 ? g_uB : g_uA);

    float d = g_dinv[wid];
    uint2 usr = uin[wid * 16 + hl];              // u self (4 features)
    float2 us01 = __half22float2(*(__half2*)&usr.x);
    float2 us23 = __half22float2(*(__half2*)&usr.y);

    float4 S = make_float4(0.f, 0.f, 0.f, 0.f);
    int s = g_roff[wid], e = g_roff[wid + 1];
    int p = s;
    for (; p + 4 <= e; p += 4) {
        int c0 = g_ccol[p + half];
        int c1 = g_ccol[p + 2 + half];
        uint2 a0 = uin[c0 * 16 + hl];
        uint2 a1 = uin[c1 * 16 + hl];
        acc_u(S, a0);
        acc_u(S, a1);
    }
    if (p + 2 <= e) {
        int c = g_ccol[p + half];
        uint2 a = uin[c * 16 + hl];
        acc_u(S, a);
        p += 2;
    }
    if (p < e) {   // odd remainder: only half 0 contributes
        int c = g_ccol[p];
        uint2 a = uin[c * 16 + hl];
        if (half == 0) acc_u(S, a);
    }
    // combine the two half-warps (same feature slots)
    S.x += __shfl_xor_sync(0xFFFFFFFFu, S.x, 16);
    S.y += __shfl_xor_sync(0xFFFFFFFFu, S.y, 16);
    S.z += __shfl_xor_sync(0xFFFFFFFFu, S.z, 16);
    S.w += __shfl_xor_sync(0xFFFFFFFFu, S.w, 16);

    float4 h0v = ((const float4*)g_h0)[wid * 16 + hl];

    float4 o;   // h'
    o.x = 0.5f * d * (S.x + us01.x) + 0.5f * h0v.x;
    o.y = 0.5f * d * (S.y + us01.y) + 0.5f * h0v.y;
    o.z = 0.5f * d * (S.z + us23.x) + 0.5f * h0v.z;
    o.w = 0.5f * d * (S.w + us23.y) + 0.5f * h0v.w;

    if (FINAL) {
        o.x = fmaxf(o.x, 0.f); o.y = fmaxf(o.y, 0.f);
        o.z = fmaxf(o.z, 0.f); o.w = fmaxf(o.w, 0.f);
        float4 wa = ((const float4*)w_att)[hl];
        float dp = o.x * wa.x + o.y * wa.y + o.z * wa.z + o.w * wa.w;
        #pragma unroll
        for (int off = 8; off > 0; off >>= 1)
            dp += __shfl_xor_sync(0xFFFFFFFFu, dp, off);
        if (lane == 0) g_v[wid] = 1.f / (1.f + expf(-(dp + b_att[0])));
        if (half == 0) ((float4*)g_hA)[wid * 16 + hl] = o;      // fp32 h
    } else {
        if (half == 0) {
            uint2* uout = (uint2*)(SRC == 0 ? g_uB : g_uA);
            __half2 lo = __floats2half2_rn(d * o.x, d * o.y);
            __half2 hi = __floats2half2_rn(d * o.z, d * o.w);
            uint2 raw;
            raw.x = *(unsigned int*)&lo;
            raw.y = *(unsigned int*)&hi;
            uout[wid * 16 + hl] = raw;                          // fp16 u'
        }
    }
}

__device__ __forceinline__ int lower_bound_i(const int* a, int n, int key) {
    int lo = 0, hi = n;
    while (lo < hi) {
        int mid = (lo + hi) >> 1;
        if (a[mid] < key) lo = mid + 1; else hi = mid;
    }
    return lo;
}

// 7) FUSED per-graph readout + MLP head + log_softmax (one block per graph,
//    128 threads). z never leaves shared memory.
__global__ void __launch_bounds__(128) k_pool_mlp(
        const int* __restrict__ batch, int n,
        const float* __restrict__ W1, const float* __restrict__ b1,
        const float* __restrict__ W2, const float* __restrict__ b2,
        const float* __restrict__ W3, const float* __restrict__ b3,
        float* __restrict__ out) {
    int g = blockIdx.x;
    int t = threadIdx.x;              // 128 threads
    __shared__ int sse[2];
    if (t == 0) sse[0] = lower_bound_i(batch, n, g);
    if (t == 1) sse[1] = lower_bound_i(batch, n, g + 1);
    __syncthreads();
    int s = sse[0], e = sse[1];

    __shared__ float red[128];
    // vmax
    float lm = -INFINITY;
    for (int i = s + t; i < e; i += 128) lm = fmaxf(lm, g_v[i]);
    red[t] = lm; __syncthreads();
    for (int o = 64; o > 0; o >>= 1) { if (t < o) red[t] = fmaxf(red[t], red[t + o]); __syncthreads(); }
    float vmax = red[0];
    __syncthreads();
    // vsum
    float ls = 0.f;
    for (int i = s + t; i < e; i += 128) ls += expf(g_v[i] - vmax);
    red[t] = ls; __syncthreads();
    for (int o = 64; o > 0; o >>= 1) { if (t < o) red[t] += red[t + o]; __syncthreads(); }
    float inv = 1.f / (red[0] + 1e-16f);
    __syncthreads();

    // pooled stats: 8 row-walkers x 16 feature lanes (float4 each)
    int hl = t & 15, r8 = t >> 4;
    const float4* h4 = (const float4*)g_hA;
    float4 gmax = make_float4(-INFINITY, -INFINITY, -INFINITY, -INFINITY);
    float4 gsum = make_float4(0.f, 0.f, 0.f, 0.f);
    for (int i = s + r8; i < e; i += 8) {
        float ev = expf(g_v[i] - vmax);
        float4 hv = h4[i * 16 + hl];
        gmax.x = fmaxf(gmax.x, hv.x); gmax.y = fmaxf(gmax.y, hv.y);
        gmax.z = fmaxf(gmax.z, hv.z); gmax.w = fmaxf(gmax.w, hv.w);
        gsum.x = fmaf(ev, hv.x, gsum.x); gsum.y = fmaf(ev, hv.y, gsum.y);
        gsum.z = fmaf(ev, hv.z, gsum.z); gsum.w = fmaf(ev, hv.w, gsum.w);
    }
    __shared__ float4 smax[128], ssum[128];
    smax[t] = gmax; ssum[t] = gsum;
    __syncthreads();

    __shared__ float sz[128];         // z = [gmp | gsp]
    if (r8 == 0) {                    // threads 0..15 finalize 4 features each
        #pragma unroll
        for (int j = 1; j < 8; j++) {
            float4 m = smax[hl + 16 * j], sv = ssum[hl + 16 * j];
            gmax.x = fmaxf(gmax.x, m.x); gmax.y = fmaxf(gmax.y, m.y);
            gmax.z = fmaxf(gmax.z, m.z); gmax.w = fmaxf(gmax.w, m.w);
            gsum.x += sv.x; gsum.y += sv.y; gsum.z += sv.z; gsum.w += sv.w;
        }
        *(float4*)&sz[hl * 4] = gmax;
        gsum.x *= inv; gsum.y *= inv; gsum.z *= inv; gsum.w *= inv;
        *(float4*)&sz[64 + hl * 4] = gsum;
    }
    __syncthreads();

    // ---- MLP head on sz (z in smem) ----
    __shared__ float s1[64], s2[32], s3[8], lse;
    if (t < 64) {
        float a = b1[t];
        #pragma unroll 8
        for (int k = 0; k < 128; k++) a = fmaf(sz[k], W1[k * 64 + t], a);
        s1[t] = fmaxf(a, 0.f);
    }
    __syncthreads();
    if (t < 32) {
        float a2 = b2[t];
        #pragma unroll 8
        for (int k = 0; k < 64; k++) a2 = fmaf(s1[k], W2[k * 32 + t], a2);
        s2[t] = fmaxf(a2, 0.f);
    }
    __syncthreads();
    if (t < 8) {
        float a3 = b3[t];
        #pragma unroll
        for (int k = 0; k < 32; k++) a3 = fmaf(s2[k], W3[k * 8 + t], a3);
        s3[t] = a3;
    }
    __syncthreads();
    if (t == 0) {
        float m = s3[0];
        for (int c = 1; c < 8; c++) m = fmaxf(m, s3[c]);
        float ss = 0.f;
        for (int c = 0; c < 8; c++) ss += expf(s3[c] - m);
        lse = m + logf(ss);
    }
    __syncthreads();
    if (t < 8) out[g * 8 + t] = s3[t] - lse;
}

extern "C" void kernel_launch(void* const* d_in, const int* in_sizes, int n_in,
                              void* d_out, int out_size) {
    const float* x     = (const float*)d_in[0];
    const int*   ei    = (const int*)  d_in[1];   // [2, E] flattened
    const int*   batch = (const int*)  d_in[2];
    const float* W_sgc = (const float*)d_in[3];
    const float* b_sgc = (const float*)d_in[4];
    const float* w_att = (const float*)d_in[5];
    const float* b_att = (const float*)d_in[6];
    const float* W1    = (const float*)d_in[7];
    const float* b1    = (const float*)d_in[8];
    const float* W2    = (const float*)d_in[9];
    const float* b2    = (const float*)d_in[10];
    const float* W3    = (const float*)d_in[11];
    const float* b3    = (const float*)d_in[12];
    float* out = (float*)d_out;

    int n = in_sizes[0] / HF;        // nodes
    int e = in_sizes[1] / 2;         // edges
    int g = out_size / 8;            // graphs

    int nb = (n + 1023) / 1024;      // 1024-element scan blocks

    k_hist<<<(e + 255) / 256, 256>>>(ei, e);                  // 1
    k_scan_bsum<<<nb, 256>>>(n);                              // 2
    k_scan_final<<<nb, 256>>>(nb, e, n);                      // 3
    k_scatter<<<(e + 255) / 256, 256>>>(ei, e);               // 4
    k_gemm<<<(n + 127) / 128, 128>>>(x, W_sgc, b_sgc, n);     // 5

    int hop_blocks = (n * 32 + 255) / 256;
    k_hop<0, false><<<hop_blocks, 256>>>(w_att, b_att, n);    // 6: uA -> uB
    k_hop<1, false><<<hop_blocks, 256>>>(w_att, b_att, n);    // 7: uB -> uA
    k_hop<2, true ><<<hop_blocks, 256>>>(w_att, b_att, n);    // 8: uA -> hA (+v)

    k_pool_mlp<<<g, 128>>>(batch, n, W1, b1, W2, b2, W3, b3, out);  // 9
}